// round 6
// baseline (speedup 1.0000x reference)
#include <cuda_runtime.h>

#define DD   256
#define HID  512
#define NPTS 100000

#define K1_BLOCKS  592
#define K1_THREADS 256
#define NSTREAM    (K1_BLOCKS * 4)       // 2368 warps per stream
#define STRIDE     (2 * NSTREAM)         // 4736 rows consumed per stream-iter
#define ITERS      ((NPTS + STRIDE - 1) / STRIDE)  // 22

#define SHIFT 40.0f   // fixed exponent shift; softmax normalization makes it exact

// Persistent scratch, zero-initialized at module load; each replay restores the
// all-zero invariant (k1 zeroes g_h; k4 re-zeroes the streaming accumulators).
__device__ float g_s;
__device__ float g_racc[DD];
__device__ float g_lacc[DD];
__device__ float g_h[HID];

// ---------------------------------------------------------------------------
// K1: warp-specialized streaming pass, software-pipelined (prefetch t+1 before
// computing t), branch-free clamped loads -> 8 LDG.128 in flight per thread.
// ---------------------------------------------------------------------------
__global__ __launch_bounds__(K1_THREADS, 4)
void k1_stream(const float* __restrict__ x_t,
               const float* __restrict__ stm_emb,
               const float* __restrict__ stm_w,
               const float* __restrict__ ltm_emb,
               const float* __restrict__ ltm_w) {
    const int lane = threadIdx.x & 31;
    const int warp = threadIdx.x >> 5;
    const int d0   = 4 * lane;
    const int NLAST = NPTS - 1;

    if (blockIdx.x == 0) {               // reset layer-1 accumulator for this replay
        for (int j = threadIdx.x; j < HID; j += K1_THREADS) g_h[j] = 0.0f;
    }

    __shared__ float sh_r[4][DD];
    __shared__ float sh_l[4][DD];
    __shared__ float sh_s[4];

    if (warp < 4) {
        // ---------------- STM stream ----------------
        const float4 xa = *(const float4*)(x_t + d0);
        const float4 xb = *(const float4*)(x_t + 128 + d0);
        const int gw = blockIdx.x * 4 + warp;

        float4 ra = make_float4(0.f, 0.f, 0.f, 0.f);
        float4 rb = make_float4(0.f, 0.f, 0.f, 0.f);
        float s_sum = 0.0f;

        int r0 = gw, r1 = gw + NSTREAM;
        const float* p0 = stm_emb + (size_t)min(r0, NLAST) * DD;
        const float* p1 = stm_emb + (size_t)min(r1, NLAST) * DD;
        float4 A0 = __ldcs((const float4*)(p0 + d0));
        float4 B0 = __ldcs((const float4*)(p0 + 128 + d0));
        float4 A1 = __ldcs((const float4*)(p1 + d0));
        float4 B1 = __ldcs((const float4*)(p1 + 128 + d0));
        float  W0 = __ldg(stm_w + min(r0, NLAST));
        float  W1 = __ldg(stm_w + min(r1, NLAST));

        #pragma unroll 1
        for (int t = 0; t < ITERS; t++) {
            // ---- prefetch iteration t+1 FIRST (unconditional, clamped) ----
            const int nr0 = r0 + STRIDE, nr1 = r1 + STRIDE;
            const float* q0 = stm_emb + (size_t)min(nr0, NLAST) * DD;
            const float* q1 = stm_emb + (size_t)min(nr1, NLAST) * DD;
            float4 nA0 = __ldcs((const float4*)(q0 + d0));
            float4 nB0 = __ldcs((const float4*)(q0 + 128 + d0));
            float4 nA1 = __ldcs((const float4*)(q1 + d0));
            float4 nB1 = __ldcs((const float4*)(q1 + 128 + d0));
            float  nW0 = __ldg(stm_w + min(nr0, NLAST));
            float  nW1 = __ldg(stm_w + min(nr1, NLAST));

            // validity as multiplicative masks (no predicated branches)
            const float m0 = (r0 < NPTS) ? 1.0f : 0.0f;
            const float m1 = (r1 < NPTS) ? 1.0f : 0.0f;

            // ---- compute iteration t ----
            float dA = A0.x*xa.x + A0.y*xa.y + A0.z*xa.z + A0.w*xa.w
                     + B0.x*xb.x + B0.y*xb.y + B0.z*xb.z + B0.w*xb.w;
            float dB = A1.x*xa.x + A1.y*xa.y + A1.z*xa.z + A1.w*xa.w
                     + B1.x*xb.x + B1.y*xb.y + B1.z*xb.z + B1.w*xb.w;
            #pragma unroll
            for (int o = 16; o > 0; o >>= 1) {
                dA += __shfl_xor_sync(0xffffffffu, dA, o);
                dB += __shfl_xor_sync(0xffffffffu, dB, o);
            }

            float pA = m0 * __expf(fmaf(dA, W0, -SHIFT));
            float pB = m1 * __expf(fmaf(dB, W1, -SHIFT));
            s_sum += pA + pB;

            ra.x = fmaf(pA, A0.x, fmaf(pB, A1.x, ra.x));
            ra.y = fmaf(pA, A0.y, fmaf(pB, A1.y, ra.y));
            ra.z = fmaf(pA, A0.z, fmaf(pB, A1.z, ra.z));
            ra.w = fmaf(pA, A0.w, fmaf(pB, A1.w, ra.w));
            rb.x = fmaf(pA, B0.x, fmaf(pB, B1.x, rb.x));
            rb.y = fmaf(pA, B0.y, fmaf(pB, B1.y, rb.y));
            rb.z = fmaf(pA, B0.z, fmaf(pB, B1.z, rb.z));
            rb.w = fmaf(pA, B0.w, fmaf(pB, B1.w, rb.w));

            // ---- rotate pipeline ----
            A0 = nA0; B0 = nB0; A1 = nA1; B1 = nB1;
            W0 = nW0; W1 = nW1; r0 = nr0; r1 = nr1;
        }

        *(float4*)&sh_r[warp][d0]       = ra;
        *(float4*)&sh_r[warp][128 + d0] = rb;
        if (lane == 0) sh_s[warp] = s_sum;
    } else {
        // ---------------- LTM stream ----------------
        const int gw = blockIdx.x * 4 + (warp - 4);

        float4 la = make_float4(0.f, 0.f, 0.f, 0.f);
        float4 lb = make_float4(0.f, 0.f, 0.f, 0.f);

        int r0 = gw, r1 = gw + NSTREAM;
        const float* p0 = ltm_emb + (size_t)min(r0, NLAST) * DD;
        const float* p1 = ltm_emb + (size_t)min(r1, NLAST) * DD;
        float4 E0 = __ldcs((const float4*)(p0 + d0));
        float4 F0 = __ldcs((const float4*)(p0 + 128 + d0));
        float4 E1 = __ldcs((const float4*)(p1 + d0));
        float4 F1 = __ldcs((const float4*)(p1 + 128 + d0));
        float  V0 = __ldg(ltm_w + min(r0, NLAST));
        float  V1 = __ldg(ltm_w + min(r1, NLAST));

        #pragma unroll 1
        for (int t = 0; t < ITERS; t++) {
            const int nr0 = r0 + STRIDE, nr1 = r1 + STRIDE;
            const float* q0 = ltm_emb + (size_t)min(nr0, NLAST) * DD;
            const float* q1 = ltm_emb + (size_t)min(nr1, NLAST) * DD;
            float4 nE0 = __ldcs((const float4*)(q0 + d0));
            float4 nF0 = __ldcs((const float4*)(q0 + 128 + d0));
            float4 nE1 = __ldcs((const float4*)(q1 + d0));
            float4 nF1 = __ldcs((const float4*)(q1 + 128 + d0));
            float  nV0 = __ldg(ltm_w + min(nr0, NLAST));
            float  nV1 = __ldg(ltm_w + min(nr1, NLAST));

            const float v0 = (r0 < NPTS) ? V0 : 0.0f;
            const float v1 = (r1 < NPTS) ? V1 : 0.0f;
            la.x = fmaf(v0, E0.x, fmaf(v1, E1.x, la.x));
            la.y = fmaf(v0, E0.y, fmaf(v1, E1.y, la.y));
            la.z = fmaf(v0, E0.z, fmaf(v1, E1.z, la.z));
            la.w = fmaf(v0, E0.w, fmaf(v1, E1.w, la.w));
            lb.x = fmaf(v0, F0.x, fmaf(v1, F1.x, lb.x));
            lb.y = fmaf(v0, F0.y, fmaf(v1, F1.y, lb.y));
            lb.z = fmaf(v0, F0.z, fmaf(v1, F1.z, lb.z));
            lb.w = fmaf(v0, F0.w, fmaf(v1, F1.w, lb.w));

            E0 = nE0; F0 = nF0; E1 = nE1; F1 = nF1;
            V0 = nV0; V1 = nV1; r0 = nr0; r1 = nr1;
        }

        *(float4*)&sh_l[warp - 4][d0]       = la;
        *(float4*)&sh_l[warp - 4][128 + d0] = lb;
    }
    __syncthreads();

    const int t = threadIdx.x;
    float rsum = sh_r[0][t] + sh_r[1][t] + sh_r[2][t] + sh_r[3][t];
    float lsum = sh_l[0][t] + sh_l[1][t] + sh_l[2][t] + sh_l[3][t];
    atomicAdd(&g_racc[t], rsum);
    atomicAdd(&g_lacc[t], lsum);
    if (t == 0) atomicAdd(&g_s, sh_s[0] + sh_s[1] + sh_s[2] + sh_s[3]);
}

// ---------------------------------------------------------------------------
// K3: h_j += sum_i fused_i * w1[i,j] — 192 blocks × 4 rows, coalesced w1 reads.
// Block 0 also seeds out = b2 (consumed only by k4's atomics, next kernel).
// ---------------------------------------------------------------------------
#define K3_BLOCKS 192
#define K3_ROWS   (3 * DD / K3_BLOCKS)  // 4

__global__ void k3_mlp1(const float* __restrict__ x_t,
                        const float* __restrict__ w1,
                        const float* __restrict__ b2,
                        float* __restrict__ out) {
    const int j = threadIdx.x;           // 512 threads, one per hidden unit
    const float inv_s = 1.0f / g_s;
    const int i0 = blockIdx.x * K3_ROWS;
    float acc = 0.0f;
    #pragma unroll
    for (int k = 0; k < K3_ROWS; k++) {
        int i = i0 + k;
        float f;
        if (i < DD)          f = x_t[i];
        else if (i < 2 * DD) f = g_racc[i - DD] * inv_s;
        else                 f = g_lacc[i - 2 * DD];
        acc = fmaf(f, w1[i * HID + j], acc);
    }
    atomicAdd(&g_h[j], acc);

    if (blockIdx.x == 0 && j < DD) out[j] = b2[j];   // seed for k4's atomics
}

// ---------------------------------------------------------------------------
// K4: out[d] += sum_j relu(h_j+b1_j) * w2[j,d] — coalesced, 128 blocks × 4 rows.
// Block 0 re-zeroes the streaming accumulators for the next replay.
// ---------------------------------------------------------------------------
#define K4_BLOCKS 128
#define K4_ROWS   (HID / K4_BLOCKS)  // 4

__global__ void k4_mlp2(const float* __restrict__ b1,
                        const float* __restrict__ w2,
                        float* __restrict__ out) {
    const int d  = threadIdx.x;          // 256 threads, one per output dim
    const int j0 = blockIdx.x * K4_ROWS;
    float acc = 0.0f;
    #pragma unroll
    for (int k = 0; k < K4_ROWS; k++) {
        int j = j0 + k;
        float h = fmaxf(g_h[j] + b1[j], 0.0f);
        acc = fmaf(h, w2[j * DD + d], acc);
    }
    atomicAdd(out + d, acc);

    if (blockIdx.x == 0) {               // restore zero-invariant for next replay
        g_racc[d] = 0.0f;
        g_lacc[d] = 0.0f;
        if (d == 0) g_s = 0.0f;
    }
}

// ---------------------------------------------------------------------------
extern "C" void kernel_launch(void* const* d_in, const int* in_sizes, int n_in,
                              void* d_out, int out_size) {
    const float* x_t     = (const float*)d_in[0];
    const float* stm_emb = (const float*)d_in[1];
    const float* stm_w   = (const float*)d_in[2];
    const float* ltm_emb = (const float*)d_in[3];
    const float* ltm_w   = (const float*)d_in[4];
    const float* w1      = (const float*)d_in[5];
    const float* b1      = (const float*)d_in[6];
    const float* w2      = (const float*)d_in[7];
    const float* b2      = (const float*)d_in[8];
    float* out = (float*)d_out;

    k1_stream<<<K1_BLOCKS, K1_THREADS>>>(x_t, stm_emb, stm_w, ltm_emb, ltm_w);
    k3_mlp1<<<K3_BLOCKS, HID>>>(x_t, w1, b2, out);
    k4_mlp2<<<K4_BLOCKS, DD>>>(b1, w2, out);
}